// round 2
// baseline (speedup 1.0000x reference)
#include <cuda_runtime.h>

// Problem constants
#define BB   4
#define NQ   196
#define NK   196
#define DMOD 512
#define NH   8
#define DK   64
#define MROWS (BB*NQ)   // 784
#define KPAD 65
#define TQ   16

// Device scratch (no allocation allowed in kernel_launch)
__device__ float g_qsig[BB*NQ*DMOD];
__device__ float g_kp[BB*NQ*DMOD];
__device__ float g_vp[BB*NQ*DMOD];
__device__ float g_img[BB*NQ*DMOD];

// ---------------------------------------------------------------------------
// Projection GEMMs: Y = X @ W^T + b for (queries,Wq,bq)->g_qsig, etc.
// M=784, N=512, K=512. blockIdx.z selects which projection.
// ---------------------------------------------------------------------------
__global__ void __launch_bounds__(256) proj_gemm_kernel(
    const float* __restrict__ Xq, const float* __restrict__ Xk, const float* __restrict__ Xv,
    const float* __restrict__ Wq, const float* __restrict__ Wk, const float* __restrict__ Wv,
    const float* __restrict__ bq, const float* __restrict__ bk, const float* __restrict__ bv)
{
    const float* X; const float* W; const float* bias; float* Y;
    if (blockIdx.z == 0)      { X = Xq; W = Wq; bias = bq; Y = g_qsig; }
    else if (blockIdx.z == 1) { X = Xk; W = Wk; bias = bk; Y = g_kp;   }
    else                      { X = Xv; W = Wv; bias = bv; Y = g_vp;   }

    __shared__ float As[16][64];
    __shared__ float Bs[16][64];

    const int tid = threadIdx.x;
    const int lr  = tid >> 2;          // 0..63 (row within tile)
    const int lc  = (tid & 3) << 2;    // 0,4,8,12 (k offset)
    const int tx  = tid & 15;
    const int ty  = tid >> 4;
    const int gm_base = blockIdx.y * 64;
    const int gn_base = blockIdx.x * 64;

    float acc[4][4];
#pragma unroll
    for (int i = 0; i < 4; i++)
#pragma unroll
        for (int j = 0; j < 4; j++) acc[i][j] = 0.f;

    for (int kt = 0; kt < DMOD; kt += 16) {
        int gm = gm_base + lr;
        float4 xv = make_float4(0.f, 0.f, 0.f, 0.f);
        if (gm < MROWS) xv = *(const float4*)(X + (long)gm * DMOD + kt + lc);
        As[lc + 0][lr] = xv.x; As[lc + 1][lr] = xv.y;
        As[lc + 2][lr] = xv.z; As[lc + 3][lr] = xv.w;

        float4 wv = *(const float4*)(W + (long)(gn_base + lr) * DMOD + kt + lc);
        Bs[lc + 0][lr] = wv.x; Bs[lc + 1][lr] = wv.y;
        Bs[lc + 2][lr] = wv.z; Bs[lc + 3][lr] = wv.w;
        __syncthreads();

#pragma unroll
        for (int kk = 0; kk < 16; kk++) {
            float4 av = *(const float4*)&As[kk][ty << 2];
            float4 bv4 = *(const float4*)&Bs[kk][tx << 2];
            float a[4] = {av.x, av.y, av.z, av.w};
            float b[4] = {bv4.x, bv4.y, bv4.z, bv4.w};
#pragma unroll
            for (int i = 0; i < 4; i++)
#pragma unroll
                for (int j = 0; j < 4; j++) acc[i][j] += a[i] * b[j];
        }
        __syncthreads();
    }

#pragma unroll
    for (int i = 0; i < 4; i++) {
        int m = gm_base + (ty << 2) + i;
        if (m >= MROWS) break;
#pragma unroll
        for (int j = 0; j < 4; j++) {
            int n = gn_base + (tx << 2) + j;
            Y[(long)m * DMOD + n] = acc[i][j] + bias[n];
        }
    }
}

// ---------------------------------------------------------------------------
// Attention core. Grid: (ceil(NQ/TQ)=13, B*H=32). 128 threads = 4 warps.
// Each block handles one (b,h) and a tile of TQ query rows.
// SMEM: K tile [196][65] (padded: pass1 reads lane-varying rows),
//       V tile [196][64], per-warp softmax buffer + q vector.
// ---------------------------------------------------------------------------
__global__ void __launch_bounds__(128) attn_kernel(const float* __restrict__ scale)
{
    extern __shared__ float sm[];
    float* Ksh  = sm;                       // NK*KPAD
    float* Vsh  = Ksh + NK * KPAD;          // NK*64
    float* pbuf = Vsh + NK * 64;            // 4*NK
    float* qsm  = pbuf + 4 * NK;            // 4*64

    const int bh   = blockIdx.y;
    const int b    = bh >> 3;
    const int h    = bh & 7;
    const int tid  = threadIdx.x;
    const int w    = tid >> 5;
    const int lane = tid & 31;

    const float* kbase = g_kp + (long)(b * NQ) * DMOD + h * DK;
    const float* vbase = g_vp + (long)(b * NQ) * DMOD + h * DK;

    // Stage K and V head-tiles into shared memory (float4 global loads).
    for (int idx = tid; idx < NK * 16; idx += 128) {
        int n  = idx >> 4;
        int c4 = (idx & 15) << 2;
        float4 kv = *(const float4*)(kbase + (long)n * DMOD + c4);
        Ksh[n * KPAD + c4 + 0] = kv.x; Ksh[n * KPAD + c4 + 1] = kv.y;
        Ksh[n * KPAD + c4 + 2] = kv.z; Ksh[n * KPAD + c4 + 3] = kv.w;
        float4 vv = *(const float4*)(vbase + (long)n * DMOD + c4);
        *(float4*)(Vsh + n * 64 + c4) = vv;
    }
    __syncthreads();

    const int q0base = blockIdx.x * TQ;
    for (int j = 0; j < 4; j++) {
        int q = q0base + w + 4 * j;
        if (q >= NQ) break;   // uniform within warp

        const float* qrow = g_qsig + (long)(b * NQ + q) * DMOD + h * DK;
        float qv0 = qrow[lane];
        float qv1 = qrow[lane + 32];
        qsm[w * 64 + lane]      = qv0;
        qsm[w * 64 + lane + 32] = qv1;
        __syncwarp();

        // Pass 1: scores. Lane l owns k = l, l+32, ... (7 slots).
        float s[7];
#pragma unroll
        for (int i = 0; i < 7; i++) s[i] = 0.f;
        int kb[7];
#pragma unroll
        for (int i = 0; i < 7; i++) kb[i] = (i * 32 + lane) * KPAD;
        // OOB rows (k up to 223) read into Vsh region — defined memory, masked later.
#pragma unroll 4
        for (int d = 0; d < 64; d++) {
            float qd = qsm[w * 64 + d];
#pragma unroll
            for (int i = 0; i < 7; i++) s[i] += qd * Ksh[kb[i] + d];
        }

        const float* scrow = scale + (long)(h * NQ + q) * NK;
        float mx = -1e30f;
#pragma unroll
        for (int i = 0; i < 7; i++) {
            int k = i * 32 + lane;
            if (k < NK) { s[i] *= scrow[k]; mx = fmaxf(mx, s[i]); }
        }
#pragma unroll
        for (int o = 16; o; o >>= 1) mx = fmaxf(mx, __shfl_xor_sync(0xffffffffu, mx, o));

        float sum = 0.f;
#pragma unroll
        for (int i = 0; i < 7; i++) {
            int k = i * 32 + lane;
            if (k < NK) {
                float p = __expf(s[i] - mx);
                pbuf[w * NK + k] = p;
                sum += p;
            }
        }
#pragma unroll
        for (int o = 16; o; o >>= 1) sum += __shfl_xor_sync(0xffffffffu, sum, o);
        float rden = __fdividef(1.f, sum);
        __syncwarp();

        // Pass 2: out_d = sum_k p_k * sigmoid(q_d*k_d) * v_d. Lane owns d=lane, lane+32.
        float a0 = 0.f, a1 = 0.f;
#pragma unroll 4
        for (int k = 0; k < NK; k++) {
            float pk = pbuf[w * NK + k];
            float e0 = qv0 * Ksh[k * KPAD + lane];
            float e1 = qv1 * Ksh[k * KPAD + lane + 32];
            // p_k * sigmoid(e) folded into one fast divide each
            float g0 = __fdividef(pk, 1.f + __expf(-e0));
            float g1 = __fdividef(pk, 1.f + __expf(-e1));
            a0 += g0 * Vsh[k * 64 + lane];
            a1 += g1 * Vsh[k * 64 + lane + 32];
        }

        float* orow = g_img + (long)(b * NQ + q) * DMOD + h * DK;
        orow[lane]      = a0 * rden;
        orow[lane + 32] = a1 * rden;
        __syncwarp();
    }
}

// ---------------------------------------------------------------------------
// Output projection + final gate: o = img @ Wo^T + bo; out = sigmoid(qsig*o)*o
// ---------------------------------------------------------------------------
__global__ void __launch_bounds__(256) out_gemm_kernel(
    const float* __restrict__ Wo, const float* __restrict__ bo, float* __restrict__ out)
{
    __shared__ float As[16][64];
    __shared__ float Bs[16][64];

    const int tid = threadIdx.x;
    const int lr  = tid >> 2;
    const int lc  = (tid & 3) << 2;
    const int tx  = tid & 15;
    const int ty  = tid >> 4;
    const int gm_base = blockIdx.y * 64;
    const int gn_base = blockIdx.x * 64;

    float acc[4][4];
#pragma unroll
    for (int i = 0; i < 4; i++)
#pragma unroll
        for (int j = 0; j < 4; j++) acc[i][j] = 0.f;

    for (int kt = 0; kt < DMOD; kt += 16) {
        int gm = gm_base + lr;
        float4 xv = make_float4(0.f, 0.f, 0.f, 0.f);
        if (gm < MROWS) xv = *(const float4*)(g_img + (long)gm * DMOD + kt + lc);
        As[lc + 0][lr] = xv.x; As[lc + 1][lr] = xv.y;
        As[lc + 2][lr] = xv.z; As[lc + 3][lr] = xv.w;

        float4 wv = *(const float4*)(Wo + (long)(gn_base + lr) * DMOD + kt + lc);
        Bs[lc + 0][lr] = wv.x; Bs[lc + 1][lr] = wv.y;
        Bs[lc + 2][lr] = wv.z; Bs[lc + 3][lr] = wv.w;
        __syncthreads();

#pragma unroll
        for (int kk = 0; kk < 16; kk++) {
            float4 av = *(const float4*)&As[kk][ty << 2];
            float4 bv4 = *(const float4*)&Bs[kk][tx << 2];
            float a[4] = {av.x, av.y, av.z, av.w};
            float b[4] = {bv4.x, bv4.y, bv4.z, bv4.w};
#pragma unroll
            for (int i = 0; i < 4; i++)
#pragma unroll
                for (int j = 0; j < 4; j++) acc[i][j] += a[i] * b[j];
        }
        __syncthreads();
    }

#pragma unroll
    for (int i = 0; i < 4; i++) {
        int m = gm_base + (ty << 2) + i;
        if (m >= MROWS) break;
#pragma unroll
        for (int j = 0; j < 4; j++) {
            int n = gn_base + (tx << 2) + j;
            float o  = acc[i][j] + bo[n];
            float qs = g_qsig[(long)m * DMOD + n];
            out[(long)m * DMOD + n] = __fdividef(o, 1.f + __expf(-qs * o));
        }
    }
}

// ---------------------------------------------------------------------------
extern "C" void kernel_launch(void* const* d_in, const int* in_sizes, int n_in,
                              void* d_out, int out_size)
{
    const float* queries = (const float*)d_in[0];
    const float* keys    = (const float*)d_in[1];
    const float* values  = (const float*)d_in[2];
    const float* Wq      = (const float*)d_in[3];
    const float* bq      = (const float*)d_in[4];
    const float* Wk      = (const float*)d_in[5];
    const float* bk      = (const float*)d_in[6];
    const float* Wv      = (const float*)d_in[7];
    const float* bv      = (const float*)d_in[8];
    const float* Wo      = (const float*)d_in[9];
    const float* bo      = (const float*)d_in[10];
    const float* scale   = (const float*)d_in[11];
    float* out = (float*)d_out;

    const int smem_attn = (NK * KPAD + NK * 64 + 4 * NK + 4 * 64) * (int)sizeof(float);
    cudaFuncSetAttribute(attn_kernel, cudaFuncAttributeMaxDynamicSharedMemorySize, smem_attn);

    dim3 g1(DMOD / 64, (MROWS + 63) / 64, 3);
    proj_gemm_kernel<<<g1, 256>>>(queries, keys, values, Wq, Wk, Wv, bq, bk, bv);

    dim3 g2((NQ + TQ - 1) / TQ, BB * NH);
    attn_kernel<<<g2, 128, smem_attn>>>(scale);

    dim3 g3(DMOD / 64, (MROWS + 63) / 64);
    out_gemm_kernel<<<g3, 256>>>(Wo, bo, out);
}